// round 14
// baseline (speedup 1.0000x reference)
#include <cuda_runtime.h>
#include <cuda_bf16.h>
#include <cstdint>

#define N_NODES 20000
#define N_EDGES 640000
#define HS 256
#define H_HEADS 8
#define DK 32
#define FF_DIM 1024
#define N_LAYERS 2

// ---------------- scratch (static device globals; no runtime alloc) ----------------
__device__ float g_q[(size_t)N_NODES * HS];
__device__ float g_k[(size_t)N_NODES * HS];
__device__ float g_tmp[(size_t)N_NODES * HS];
__device__ float g_h[(size_t)N_NODES * HS];
__device__ float g_xbuf[(size_t)N_NODES * HS];

// bf16 pair-word activation buffers: word i = {val[2i], val[2i+1]} (row-major bf16)
__device__ __align__(16) uint32_t g_xbf[(size_t)N_NODES * HS / 2];
__device__ __align__(16) uint32_t g_vbf[(size_t)N_NODES * HS / 2];
__device__ __align__(16) uint32_t g_obf[(size_t)N_NODES * HS / 2];
__device__ __align__(16) uint32_t g_hbf[(size_t)N_NODES * HS / 2];
__device__ __align__(16) uint32_t g_ffbf[(size_t)N_NODES * FF_DIM / 2];

// k-major bf16 weights: word(k, n2) = {W[k][2*n2], W[k][2*n2+1]} at [k * Nc/2 + n2]
#define WQ_OFF 0
#define WK_OFF 32768
#define WV_OFF 65536
#define WO_OFF 98304
#define W1_OFF 131072
#define W2_OFF 262144
#define WL_STRIDE 393216
__device__ __align__(16) uint32_t g_wbf[2 * WL_STRIDE];

__device__ int g_cnt[N_NODES];
__device__ int g_rowptr[N_NODES + 1];
__device__ int g_cursor[N_NODES];
__device__ int g_eids[N_EDGES];

__device__ __forceinline__ uint32_t packbf2(float lo, float hi) {
    __nv_bfloat162 h = __float22bfloat162_rn(make_float2(lo, hi));
    return *reinterpret_cast<uint32_t*>(&h);
}

__device__ __forceinline__ float2 unpackbf2(uint32_t w) {
    return __bfloat1622float2(*reinterpret_cast<__nv_bfloat162*>(&w));
}

// ---------------- fused prep: convert_x + convert_weights + dst histogram ----------------
#define NXW (N_NODES * HS / 2)
__global__ void prep_kernel(const float* __restrict__ x,
                            const float* __restrict__ Wq, const float* __restrict__ Wk,
                            const float* __restrict__ Wv, const float* __restrict__ Wo,
                            const float* __restrict__ W1, const float* __restrict__ W2,
                            const int* __restrict__ dst) {
    int i = blockIdx.x * blockDim.x + threadIdx.x;
    if (i < NXW) {
        g_xbf[i] = packbf2(x[2 * i], x[2 * i + 1]);
        return;
    }
    i -= NXW;
    if (i < 2 * WL_STRIDE) {
        int layer = i / WL_STRIDE;
        int r = i % WL_STRIDE;
        const float* src;
        int kk, n2, Nc;
        if (r < W1_OFF) {
            int m = r >> 15; int rr = r & 32767; Nc = HS;
            kk = rr >> 7; n2 = rr & 127;
            src = (m == 0 ? Wq : m == 1 ? Wk : m == 2 ? Wv : Wo) + (size_t)layer * HS * HS;
        } else if (r < W2_OFF) {
            int rr = r - W1_OFF; Nc = FF_DIM;
            kk = rr >> 9; n2 = rr & 511;
            src = W1 + (size_t)layer * HS * FF_DIM;
        } else {
            int rr = r - W2_OFF; Nc = HS;
            kk = rr >> 7; n2 = rr & 127;
            src = W2 + (size_t)layer * FF_DIM * HS;
        }
        const float* p = src + (size_t)kk * Nc + 2 * n2;
        g_wbf[i] = packbf2(p[0], p[1]);
        return;
    }
    i -= 2 * WL_STRIDE;
    if (i < N_EDGES) atomicAdd(&g_cnt[dst[i]], 1);
}

// ---------------- single-pass scan: 1024 threads x 20 serial elems, 3 barriers ----------------
#define SCAN_PER 20
__global__ void scan_kernel() {
    __shared__ int wsum[32];
    __shared__ int woff[32];
    __shared__ int total_sh;
    const int tid = threadIdx.x, lane = tid & 31, wid = tid >> 5;
    const int base = tid * SCAN_PER;

    int vals[SCAN_PER];
    int s = 0;
    #pragma unroll
    for (int j = 0; j < SCAN_PER; j++) {
        int i = base + j;
        int v = (i < N_NODES) ? g_cnt[i] : 0;
        vals[j] = v; s += v;
    }
    int incl = s;
    #pragma unroll
    for (int off = 1; off < 32; off <<= 1) {
        int t = __shfl_up_sync(0xffffffffu, incl, off);
        if (lane >= off) incl += t;
    }
    if (lane == 31) wsum[wid] = incl;
    __syncthreads();
    if (wid == 0) {
        int t = wsum[lane];
        int si = t;
        #pragma unroll
        for (int off = 1; off < 32; off <<= 1) {
            int u = __shfl_up_sync(0xffffffffu, si, off);
            if (lane >= off) si += u;
        }
        woff[lane] = si - t;
        if (lane == 31) total_sh = si;
    }
    __syncthreads();
    int run = incl - s + woff[wid];
    #pragma unroll
    for (int j = 0; j < SCAN_PER; j++) {
        int i = base + j;
        if (i < N_NODES) {
            g_rowptr[i] = run;
            g_cursor[i] = run;
        }
        run += vals[j];
    }
    if (tid == 0) g_rowptr[N_NODES] = total_sh;
}

__global__ void scatter_kernel(const int* __restrict__ dst) {
    int i = blockIdx.x * blockDim.x + threadIdx.x;
    if (i < N_EDGES) {
        int p = atomicAdd(&g_cursor[dst[i]], 1);
        g_eids[p] = i;
    }
}

// ---------------- BF16 TC GEMM: 3-stage cp.async + ldmatrix, persistent CTAs ----------------
// A: row-major bf16 (pair-words [m][K/2]) ; B: k-major bf16 (pair-words [k][Nc/2]).
// Chunk = 64 k. Stage = 32KB (A 16KB + B 16KB) x 3 stages. XOR-(row&7) 16B-group swizzle.
// MODE 0: +bias (nullable)   MODE 1: relu(+bias)   MODE 2: +bias +res
#define BM 128
#define BN 128
#define GEMM_SMEM_BYTES 98304   // 3 x 32KB stages
#define STG_BYTES 32768u

__device__ __forceinline__ void cp_async16(uint32_t dst, const void* src, uint32_t sz) {
    asm volatile("cp.async.ca.shared.global [%0], [%1], 16, %2;"
                 :: "r"(dst), "l"(src), "r"(sz) : "memory");
}
__device__ __forceinline__ void cp_commit() {
    asm volatile("cp.async.commit_group;" ::: "memory");
}
__device__ __forceinline__ void cp_wait1() {
    asm volatile("cp.async.wait_group 1;" ::: "memory");
}
__device__ __forceinline__ void cp_wait0() {
    asm volatile("cp.async.wait_group 0;" ::: "memory");
}

__device__ __forceinline__ uint32_t smem_u32(const void* p) {
    uint32_t a;
    asm("{ .reg .u64 t; cvta.to.shared.u64 t, %1; cvt.u32.u64 %0, t; }" : "=r"(a) : "l"(p));
    return a;
}

#define LDMX4(r0, r1, r2, r3, addr) \
    asm volatile("ldmatrix.sync.aligned.m8n8.x4.shared.b16 {%0,%1,%2,%3}, [%4];" \
                 : "=r"(r0), "=r"(r1), "=r"(r2), "=r"(r3) : "r"(addr))

#define LDMX4T(r0, r1, r2, r3, addr) \
    asm volatile("ldmatrix.sync.aligned.m8n8.x4.trans.shared.b16 {%0,%1,%2,%3}, [%4];" \
                 : "=r"(r0), "=r"(r1), "=r"(r2), "=r"(r3) : "r"(addr))

__device__ __forceinline__ void mma_bf16(float4& c, const uint32_t a[4], const uint32_t b[2]) {
    asm volatile(
        "mma.sync.aligned.m16n8k16.row.col.f32.bf16.bf16.f32 "
        "{%0,%1,%2,%3}, {%4,%5,%6,%7}, {%8,%9}, {%0,%1,%2,%3};"
        : "+f"(c.x), "+f"(c.y), "+f"(c.z), "+f"(c.w)
        : "r"(a[0]), "r"(a[1]), "r"(a[2]), "r"(a[3]), "r"(b[0]), "r"(b[1]));
}

template <int MODE, bool OUTBF>
__device__ __forceinline__ void gemm_tile(
    uint32_t sbase,                        // smem byte base (cvta'd, 1KB aligned)
    int M, int K, int Nc, int m0, int n0,
    const uint32_t* __restrict__ Aw,       // [m][K/2]
    const uint32_t* __restrict__ Bw,       // [k][Nc/2]
    const float* __restrict__ bias,
    const float* __restrict__ res,
    float* __restrict__ C,
    uint32_t* __restrict__ Cbf)
{
    const int tid  = threadIdx.x;
    const int lane = tid & 31;
    const int warp = tid >> 5;
    const int g  = lane >> 2;
    const int tg = lane & 3;
    const int wm = (warp >> 2) * 64;
    const int wn = (warp & 3) * 32;

    const int Khalf = K >> 1;
    const int Nhalf = Nc >> 1;
    const int nch = K >> 6;                // 64-k chunks

    // ---- fill thread mapping ----
    const int fa_row = tid >> 1;           // 0..127
    const int fa_h0  = (tid & 1) * 4;      // group base 0/4
    const int fb_row = tid >> 2;           // 0..63 (k row within chunk)
    const int fb_h0  = (tid & 3) * 4;      // group base 0..12

    const int arow_g   = m0 + fa_row;
    const uint32_t asz = (arow_g < M) ? 16u : 0u;
    const uint32_t* aSrcRow = Aw + (size_t)((arow_g < M) ? arow_g : (M - 1)) * Khalf + fa_h0 * 4;
    const uint32_t aDst0 = sbase + fa_row * 128;
    const uint32_t* bSrcRow0 = Bw + (size_t)fb_row * Nhalf + (n0 >> 1) + fb_h0 * 4;
    const uint32_t bDst0 = sbase + 16384 + fb_row * 256;

    // ---- ldmatrix addresses (h=0 / ks=0), lane-static ----
    const int lr = lane & 7;
    const int mi = lane >> 3;
    const int hs = lane >> 4;              // 0/1 : k-half select for A
    uint32_t aAddr0[4];
    #pragma unroll
    for (int mt = 0; mt < 4; mt++) {
        int r = wm + mt * 16 + lr + (mi & 1) * 8;
        aAddr0[mt] = sbase + r * 128 + ((r & 7) << 4);
    }
    uint32_t bAddr0[2];
    #pragma unroll
    for (int np = 0; np < 2; np++) {
        int kR = (mi >> 1) * 8 + lr;                   // k row within k16
        int hB = (wn >> 3) + np * 2 + (mi & 1);        // n-group
        bAddr0[np] = sbase + 16384 + kR * 256 + ((hB ^ lr) << 4);
    }

    float4 acc[4][4];
    #pragma unroll
    for (int i = 0; i < 4; i++)
        #pragma unroll
        for (int j = 0; j < 4; j++) acc[i][j] = make_float4(0.f, 0.f, 0.f, 0.f);

    // ---- fill macro body (chunk c into stage buffer s*STG_BYTES) ----
    auto fill_chunk = [&](int c, uint32_t soff) {
        const int kw0 = c * 32;                        // A pair-word offset
        #pragma unroll
        for (int j = 0; j < 4; j++) {
            int h = fa_h0 + j;
            cp_async16(aDst0 + soff + ((h ^ (fa_row & 7)) << 4), aSrcRow + kw0 + j * 4, asz);
        }
        const size_t bk = (size_t)c * 64 * Nhalf;      // B k-row advance
        #pragma unroll
        for (int j = 0; j < 4; j++) {
            int h = fb_h0 + j;
            cp_async16(bDst0 + soff + ((h ^ (fb_row & 7)) << 4), bSrcRow0 + bk + j * 4, 16u);
        }
        cp_commit();
    };

    // ---- prologue: fill chunks 0,1 into stages 0,1 ----
    fill_chunk(0, 0u);
    if (nch > 1) fill_chunk(1, STG_BYTES);

    for (int ch = 0; ch < nch; ch++) {
        const uint32_t soff = (uint32_t)(ch % 3) * STG_BYTES;

        if (ch <= nch - 2) cp_wait1(); else cp_wait0();
        __syncthreads();

        #pragma unroll
        for (int ks = 0; ks < 4; ks++) {
            uint32_t afr[4][4];
            uint32_t bfr[4][2];
            const uint32_t hxor = (uint32_t)((2 * ks + hs) << 4);
            #pragma unroll
            for (int mt = 0; mt < 4; mt++)
                LDMX4(afr[mt][0], afr[mt][1], afr[mt][2], afr[mt][3],
                      (aAddr0[mt] + soff) ^ hxor);
            #pragma unroll
            for (int np = 0; np < 2; np++) {
                uint32_t r0, r1, r2, r3;
                LDMX4T(r0, r1, r2, r3, bAddr0[np] + soff + ks * 4096);
                bfr[2 * np][0] = r0; bfr[2 * np][1] = r2;
                bfr[2 * np + 1][0] = r1; bfr[2 * np + 1][1] = r3;
            }
            #pragma unroll
            for (int mt = 0; mt < 4; mt++)
                #pragma unroll
                for (int nt = 0; nt < 4; nt++)
                    mma_bf16(acc[mt][nt], afr[mt], bfr[nt]);
        }

        if (ch + 2 < nch)
            fill_chunk(ch + 2, (uint32_t)((ch + 2) % 3) * STG_BYTES);
    }

    // ---- epilogue ----
    #pragma unroll
    for (int mt = 0; mt < 4; mt++) {
        #pragma unroll
        for (int nt = 0; nt < 4; nt++) {
            const int row0 = m0 + wm + mt * 16 + g;
            const int row1 = row0 + 8;
            const int col  = n0 + wn + nt * 8 + tg * 2;
            float2 v0 = make_float2(acc[mt][nt].x, acc[mt][nt].y);
            float2 v1 = make_float2(acc[mt][nt].z, acc[mt][nt].w);
            if (bias) {
                float2 bb = *(const float2*)(bias + col);
                v0.x += bb.x; v0.y += bb.y;
                v1.x += bb.x; v1.y += bb.y;
            }
            if (MODE == 2) {
                if (row0 < M) {
                    float2 r0 = *(const float2*)(res + (size_t)row0 * Nc + col);
                    v0.x += r0.x; v0.y += r0.y;
                }
                if (row1 < M) {
                    float2 r1 = *(const float2*)(res + (size_t)row1 * Nc + col);
                    v1.x += r1.x; v1.y += r1.y;
                }
            }
            if (MODE == 1) {
                v0.x = fmaxf(v0.x, 0.f); v0.y = fmaxf(v0.y, 0.f);
                v1.x = fmaxf(v1.x, 0.f); v1.y = fmaxf(v1.y, 0.f);
            }
            if (OUTBF) {
                if (row0 < M) Cbf[(size_t)row0 * (Nc >> 1) + (col >> 1)] = packbf2(v0.x, v0.y);
                if (row1 < M) Cbf[(size_t)row1 * (Nc >> 1) + (col >> 1)] = packbf2(v1.x, v1.y);
            } else {
                if (row0 < M) *(float2*)(C + (size_t)row0 * Nc + col) = v0;
                if (row1 < M) *(float2*)(C + (size_t)row1 * Nc + col) = v1;
            }
        }
    }
}

template <int MODE, bool OUTBF>
__global__ __launch_bounds__(256, 2) void bf16_gemm_kernel(
    int M, int K, int Nc, int gn, int total_tiles,
    const uint32_t* __restrict__ Aw,
    const uint32_t* __restrict__ Bw,
    const float* __restrict__ bias,
    const float* __restrict__ res,
    float* __restrict__ C,
    uint32_t* __restrict__ Cbf)
{
    extern __shared__ __align__(1024) uint32_t dynsmem[];
    const uint32_t sbase = smem_u32(dynsmem);
    for (int t = blockIdx.x; t < total_tiles; t += gridDim.x) {
        const int m0 = (t / gn) * BM;
        const int n0 = (t % gn) * BN;
        __syncthreads();   // protect smem stage reuse across tiles
        gemm_tile<MODE, OUTBF>(sbase, M, K, Nc, m0, n0, Aw, Bw, bias, res, C, Cbf);
    }
}

// fused q/k/v: q,k -> fp32 ; v -> bf16 pair-words
__global__ __launch_bounds__(256, 2) void bf16_gemm_qkv_kernel(
    int M, int K, int Nc, int gn, int tiles_per,
    const uint32_t* __restrict__ Aw,
    const uint32_t* __restrict__ Bq,
    const uint32_t* __restrict__ Bk,
    const uint32_t* __restrict__ Bv,
    const float* __restrict__ biasq,
    float* __restrict__ Cq,
    float* __restrict__ Ck,
    uint32_t* __restrict__ Cvbf)
{
    extern __shared__ __align__(1024) uint32_t dynsmem[];
    const uint32_t sbase = smem_u32(dynsmem);
    const int total = 3 * tiles_per;
    for (int t = blockIdx.x; t < total; t += gridDim.x) {
        const int which = t / tiles_per;
        const int tt = t % tiles_per;
        const int m0 = (tt / gn) * BM;
        const int n0 = (tt % gn) * BN;
        __syncthreads();   // protect smem stage reuse across tiles
        if (which == 2) {
            gemm_tile<0, true>(sbase, M, K, Nc, m0, n0, Aw, Bv, nullptr, nullptr, nullptr, Cvbf);
        } else {
            const uint32_t* B = (which == 0) ? Bq : Bk;
            float* C          = (which == 0) ? Cq : Ck;
            const float* bias = (which == 0) ? biasq : nullptr;
            gemm_tile<0, false>(sbase, M, K, Nc, m0, n0, Aw, B, bias, nullptr, C, nullptr);
        }
    }
}

// ---------------- edge aggregation: one warp per destination node ----------------
__global__ void edge_agg_kernel(const float* __restrict__ rel,
                                const int* __restrict__ edge_feat,
                                const int* __restrict__ src)
{
    int gw = (blockIdx.x * blockDim.x + threadIdx.x) >> 5;
    int lane = threadIdx.x & 31;
    if (gw >= N_NODES) return;

    const float4* qr = (const float4*)(g_q + (size_t)gw * HS);
    float4 q0 = qr[2 * lane], q1 = qr[2 * lane + 1];

    float4 a0 = make_float4(0.f, 0.f, 0.f, 0.f);
    float4 a1 = make_float4(0.f, 0.f, 0.f, 0.f);
    float zsum = 0.f;

    const int beg = g_rowptr[gw], end = g_rowptr[gw + 1];
    const int ecol = 2 * (lane & 3);
    const float invs = 0.17677669529663687f;  // 1/sqrt(32)

    for (int base = beg; base < end; base += 32) {
        const int cnt = min(32, end - base);
        int s_l = 0, r_l = 0;
        if (base + lane < end) {
            int e = g_eids[base + lane];
            s_l = __ldg(&src[e]);
            r_l = __ldg(&edge_feat[e]);
        }

        int s_c = __shfl_sync(0xffffffffu, s_l, 0);
        int r_c = __shfl_sync(0xffffffffu, r_l, 0);
        const float4* kr = (const float4*)(g_k + (size_t)s_c * HS);
        const float4* er = (const float4*)(rel + (size_t)r_c * DK);
        float4 k0 = kr[2 * lane], k1 = kr[2 * lane + 1];
        uint4  vw = *(const uint4*)(g_vbf + (size_t)s_c * (HS / 2) + 4 * lane);
        float4 e0 = er[ecol],     e1 = er[ecol + 1];

        for (int j = 0; j < cnt; j++) {
            float4 K0 = k0, K1 = k1, E0 = e0, E1 = e1;
            uint4  VW = vw;
            if (j + 1 < cnt) {
                int s_n = __shfl_sync(0xffffffffu, s_l, j + 1);
                int r_n = __shfl_sync(0xffffffffu, r_l, j + 1);
                const float4* krn = (const float4*)(g_k + (size_t)s_n * HS);
                const float4* ern = (const float4*)(rel + (size_t)r_n * DK);
                k0 = krn[2 * lane]; k1 = krn[2 * lane + 1];
                vw = *(const uint4*)(g_vbf + (size_t)s_n * (HS / 2) + 4 * lane);
                e0 = ern[ecol];     e1 = ern[ecol + 1];
            }

            float d = (K0.x + E0.x) * q0.x + (K0.y + E0.y) * q0.y
                    + (K0.z + E0.z) * q0.z + (K0.w + E0.w) * q0.w
                    + (K1.x + E1.x) * q1.x + (K1.y + E1.y) * q1.y
                    + (K1.z + E1.z) * q1.z + (K1.w + E1.w) * q1.w;
            d += __shfl_xor_sync(0xffffffffu, d, 1);
            d += __shfl_xor_sync(0xffffffffu, d, 2);
            float sc = __expf(fminf(fmaxf(d * invs, -10.f), 10.f));

            float2 p0 = unpackbf2(VW.x), p1 = unpackbf2(VW.y);
            float2 p2 = unpackbf2(VW.z), p3 = unpackbf2(VW.w);
            a0.x += (p0.x + E0.x) * sc; a0.y += (p0.y + E0.y) * sc;
            a0.z += (p1.x + E0.z) * sc; a0.w += (p1.y + E0.w) * sc;
            a1.x += (p2.x + E1.x) * sc; a1.y += (p2.y + E1.y) * sc;
            a1.z += (p3.x + E1.z) * sc; a1.w += (p3.y + E1.w) * sc;
            zsum += sc;
        }
    }

    float inv = 1.f / zsum;
    uint4 w;
    w.x = packbf2(a0.x * inv, a0.y * inv);
    w.y = packbf2(a0.z * inv, a0.w * inv);
    w.z = packbf2(a1.x * inv, a1.y * inv);
    w.w = packbf2(a1.z * inv, a1.w * inv);
    *(uint4*)(g_obf + (size_t)gw * (HS / 2) + 4 * lane) = w;
}

// ---------------- layernorm: one warp per row; optional bf16 dual-write ----------------
__global__ void ln_kernel(const float* __restrict__ in,
                          const float* __restrict__ gamma,
                          const float* __restrict__ beta,
                          float* __restrict__ out,
                          uint32_t* __restrict__ outbf)
{
    int gw = (blockIdx.x * blockDim.x + threadIdx.x) >> 5;
    int lane = threadIdx.x & 31;
    if (gw >= N_NODES) return;

    const float4* row = (const float4*)(in + (size_t)gw * HS);
    float4 x0 = row[2 * lane], x1 = row[2 * lane + 1];

    float s = x0.x + x0.y + x0.z + x0.w + x1.x + x1.y + x1.z + x1.w;
    #pragma unroll
    for (int off = 16; off; off >>= 1) s += __shfl_xor_sync(0xffffffffu, s, off);
    float mean = s * (1.f / HS);

    float d0 = x0.x - mean, d1 = x0.y - mean, d2 = x0.z - mean, d3 = x0.w - mean;
    float d4 = x1.x - mean, d5 = x1.y - mean, d6 = x1.z - mean, d7 = x1.w - mean;
    float ss = d0 * d0 + d1 * d1 + d2 * d2 + d3 * d3 + d4 * d4 + d5 * d5 + d6 * d6 + d7 * d7;
    #pragma unroll
    for (int off = 16; off; off >>= 1) ss += __shfl_xor_sync(0xffffffffu, ss, off);
    float rstd = rsqrtf(ss * (1.f / HS) + 1e-5f);

    const float4* gr = (const float4*)gamma;
    const float4* br = (const float4*)beta;
    float4 gg0 = gr[2 * lane], gg1 = gr[2 * lane + 1];
    float4 bb0 = br[2 * lane], bb1 = br[2 * lane + 1];

    float o0 = d0 * rstd * gg0.x + bb0.x;
    float o1 = d1 * rstd * gg0.y + bb0.y;
    float o2 = d2 * rstd * gg0.z + bb0.z;
    float o3 = d3 * rstd * gg0.w + bb0.w;
    float o4 = d4 * rstd * gg1.x + bb1.x;
    float o5 = d5 * rstd * gg1.y + bb1.y;
    float o6 = d6 * rstd * gg1.z + bb1.z;
    float o7 = d7 * rstd * gg1.w + bb1.w;

    float4* orow = (float4*)(out + (size_t)gw * HS);
    orow[2 * lane]     = make_float4(o0, o1, o2, o3);
    orow[2 * lane + 1] = make_float4(o4, o5, o6, o7);

    if (outbf) {
        uint4 w;
        w.x = packbf2(o0, o1); w.y = packbf2(o2, o3);
        w.z = packbf2(o4, o5); w.w = packbf2(o6, o7);
        *(uint4*)(outbf + (size_t)gw * (HS / 2) + 4 * lane) = w;
    }
}

// ---------------- host orchestration ----------------
extern "C" void kernel_launch(void* const* d_in, const int* in_sizes, int n_in,
                              void* d_out, int out_size)
{
    const float* x_in     = (const float*)d_in[0];
    const int*   edge_feat= (const int*)  d_in[1];
    const int*   src      = (const int*)  d_in[2];
    const int*   dst      = (const int*)  d_in[3];
    const float* rel      = (const float*)d_in[4];
    const float* Wq       = (const float*)d_in[5];
    const float* bq       = (const float*)d_in[6];
    const float* Wk       = (const float*)d_in[7];
    const float* Wv       = (const float*)d_in[8];
    const float* Wo       = (const float*)d_in[9];
    const float* bo       = (const float*)d_in[10];
    const float* W1       = (const float*)d_in[11];
    const float* b1       = (const float*)d_in[12];
    const float* W2       = (const float*)d_in[13];
    const float* b2       = (const float*)d_in[14];
    const float* ln1g     = (const float*)d_in[15];
    const float* ln1b     = (const float*)d_in[16];
    const float* ln2g     = (const float*)d_in[17];
    const float* ln2b     = (const float*)d_in[18];

    float *q, *k, *tmp, *h, *xbuf;
    uint32_t *xbf, *vbf, *obf, *hbf, *ffbf, *wbf;
    int* cnt;
    cudaGetSymbolAddress((void**)&q,    g_q);
    cudaGetSymbolAddress((void**)&k,    g_k);
    cudaGetSymbolAddress((void**)&tmp,  g_tmp);
    cudaGetSymbolAddress((void**)&h,    g_h);
    cudaGetSymbolAddress((void**)&xbuf, g_xbuf);
    cudaGetSymbolAddress((void**)&xbf,  g_xbf);
    cudaGetSymbolAddress((void**)&vbf,  g_vbf);
    cudaGetSymbolAddress((void**)&obf,  g_obf);
    cudaGetSymbolAddress((void**)&hbf,  g_hbf);
    cudaGetSymbolAddress((void**)&ffbf, g_ffbf);
    cudaGetSymbolAddress((void**)&wbf,  g_wbf);
    cudaGetSymbolAddress((void**)&cnt,  g_cnt);

    // opt-in to 96KB dynamic smem (idempotent; not a stream op)
    cudaFuncSetAttribute(bf16_gemm_qkv_kernel,
                         cudaFuncAttributeMaxDynamicSharedMemorySize, GEMM_SMEM_BYTES);
    cudaFuncSetAttribute(bf16_gemm_kernel<2, false>,
                         cudaFuncAttributeMaxDynamicSharedMemorySize, GEMM_SMEM_BYTES);
    cudaFuncSetAttribute(bf16_gemm_kernel<1, true>,
                         cudaFuncAttributeMaxDynamicSharedMemorySize, GEMM_SMEM_BYTES);

    // CSR + conversions
    cudaMemsetAsync(cnt, 0, N_NODES * sizeof(int));
    const int prep_items = NXW + 2 * WL_STRIDE + N_EDGES;
    prep_kernel<<<(prep_items + 255) / 256, 256>>>(x_in, Wq, Wk, Wv, Wo, W1, W2, dst);
    scan_kernel<<<1, 1024>>>();
    scatter_kernel<<<(N_EDGES + 255) / 256, 256>>>(dst);

    const int warp_blocks = (N_NODES * 32 + 255) / 256;
    const int GM = (N_NODES + BM - 1) / BM;   // 157
    const int gnHS = HS / BN;                  // 2
    const int gnFF = FF_DIM / BN;              // 8
    const int tilesHS = GM * gnHS;             // 314
    const int tilesFF = GM * gnFF;             // 1256
    const int PGRID = 296;

    const float* xres = x_in;
    for (int l = 0; l < N_LAYERS; l++) {
        const uint32_t* wl = wbf + (size_t)l * WL_STRIDE;

        bf16_gemm_qkv_kernel<<<PGRID, 256, GEMM_SMEM_BYTES>>>(
            N_NODES, HS, HS, gnHS, tilesHS,
            xbf, wl + WQ_OFF, wl + WK_OFF, wl + WV_OFF,
            bq + l * HS, q, k, vbf);

        edge_agg_kernel<<<warp_blocks, 256>>>(rel, edge_feat, src);

        bf16_gemm_kernel<2, false><<<PGRID, 256, GEMM_SMEM_BYTES>>>(
            N_NODES, HS, HS, gnHS, tilesHS,
            obf, wl + WO_OFF, bo + l * HS, xres, tmp, nullptr);
        ln_kernel<<<warp_blocks, 256>>>(tmp, ln1g + l * HS, ln1b + l * HS, h, hbf);

        bf16_gemm_kernel<1, true><<<PGRID, 256, GEMM_SMEM_BYTES>>>(
            N_NODES, HS, FF_DIM, gnFF, tilesFF,
            hbf, wl + W1_OFF, b1 + l * FF_DIM, nullptr, nullptr, ffbf);
        bf16_gemm_kernel<2, false><<<PGRID, 256, GEMM_SMEM_BYTES>>>(
            N_NODES, FF_DIM, HS, gnHS, tilesHS,
            ffbf, wl + W2_OFF, b2 + l * HS, h, tmp, nullptr);

        if (l == N_LAYERS - 1) {
            ln_kernel<<<warp_blocks, 256>>>(tmp, ln2g + l * HS, ln2b + l * HS, (float*)d_out, nullptr);
        } else {
            ln_kernel<<<warp_blocks, 256>>>(tmp, ln2g + l * HS, ln2b + l * HS, xbuf, xbf);
            xres = xbuf;
        }
    }
}

// round 15
// speedup vs baseline: 1.0037x; 1.0037x over previous
#include <cuda_runtime.h>
#include <cuda_bf16.h>
#include <cstdint>

#define N_NODES 20000
#define N_EDGES 640000
#define HS 256
#define H_HEADS 8
#define DK 32
#define FF_DIM 1024
#define N_LAYERS 2

// ---------------- scratch (static device globals; no runtime alloc) ----------------
__device__ float g_q[(size_t)N_NODES * HS];
__device__ float g_tmp[(size_t)N_NODES * HS];
__device__ float g_h[(size_t)N_NODES * HS];
__device__ float g_xbuf[(size_t)N_NODES * HS];

// bf16 pair-word activation buffers: word i = {val[2i], val[2i+1]} (row-major bf16)
__device__ __align__(16) uint32_t g_xbf[(size_t)N_NODES * HS / 2];
__device__ __align__(16) uint32_t g_kbf[(size_t)N_NODES * HS / 2];
__device__ __align__(16) uint32_t g_vbf[(size_t)N_NODES * HS / 2];
__device__ __align__(16) uint32_t g_obf[(size_t)N_NODES * HS / 2];
__device__ __align__(16) uint32_t g_hbf[(size_t)N_NODES * HS / 2];
__device__ __align__(16) uint32_t g_ffbf[(size_t)N_NODES * FF_DIM / 2];

// k-major bf16 weights: word(k, n2) = {W[k][2*n2], W[k][2*n2+1]} at [k * Nc/2 + n2]
#define WQ_OFF 0
#define WK_OFF 32768
#define WV_OFF 65536
#define WO_OFF 98304
#define W1_OFF 131072
#define W2_OFF 262144
#define WL_STRIDE 393216
__device__ __align__(16) uint32_t g_wbf[2 * WL_STRIDE];

__device__ int g_cnt[N_NODES];
__device__ int g_rowptr[N_NODES + 1];
__device__ int g_cursor[N_NODES];
__device__ int g_eids[N_EDGES];

__device__ __forceinline__ uint32_t packbf2(float lo, float hi) {
    __nv_bfloat162 h = __float22bfloat162_rn(make_float2(lo, hi));
    return *reinterpret_cast<uint32_t*>(&h);
}

__device__ __forceinline__ float2 unpackbf2(uint32_t w) {
    return __bfloat1622float2(*reinterpret_cast<__nv_bfloat162*>(&w));
}

// ---------------- fused prep: convert_x + convert_weights + dst histogram ----------------
#define NXW (N_NODES * HS / 2)
__global__ void prep_kernel(const float* __restrict__ x,
                            const float* __restrict__ Wq, const float* __restrict__ Wk,
                            const float* __restrict__ Wv, const float* __restrict__ Wo,
                            const float* __restrict__ W1, const float* __restrict__ W2,
                            const int* __restrict__ dst) {
    int i = blockIdx.x * blockDim.x + threadIdx.x;
    if (i < NXW) {
        g_xbf[i] = packbf2(x[2 * i], x[2 * i + 1]);
        return;
    }
    i -= NXW;
    if (i < 2 * WL_STRIDE) {
        int layer = i / WL_STRIDE;
        int r = i % WL_STRIDE;
        const float* src;
        int kk, n2, Nc;
        if (r < W1_OFF) {
            int m = r >> 15; int rr = r & 32767; Nc = HS;
            kk = rr >> 7; n2 = rr & 127;
            src = (m == 0 ? Wq : m == 1 ? Wk : m == 2 ? Wv : Wo) + (size_t)layer * HS * HS;
        } else if (r < W2_OFF) {
            int rr = r - W1_OFF; Nc = FF_DIM;
            kk = rr >> 9; n2 = rr & 511;
            src = W1 + (size_t)layer * HS * FF_DIM;
        } else {
            int rr = r - W2_OFF; Nc = HS;
            kk = rr >> 7; n2 = rr & 127;
            src = W2 + (size_t)layer * FF_DIM * HS;
        }
        const float* p = src + (size_t)kk * Nc + 2 * n2;
        g_wbf[i] = packbf2(p[0], p[1]);
        return;
    }
    i -= 2 * WL_STRIDE;
    if (i < N_EDGES) atomicAdd(&g_cnt[dst[i]], 1);
}

// ---------------- single-pass scan: 1024 threads x 20 serial elems, 3 barriers ----------------
#define SCAN_PER 20
__global__ void scan_kernel() {
    __shared__ int wsum[32];
    __shared__ int woff[32];
    __shared__ int total_sh;
    const int tid = threadIdx.x, lane = tid & 31, wid = tid >> 5;
    const int base = tid * SCAN_PER;

    int vals[SCAN_PER];
    int s = 0;
    #pragma unroll
    for (int j = 0; j < SCAN_PER; j++) {
        int i = base + j;
        int v = (i < N_NODES) ? g_cnt[i] : 0;
        vals[j] = v; s += v;
    }
    int incl = s;
    #pragma unroll
    for (int off = 1; off < 32; off <<= 1) {
        int t = __shfl_up_sync(0xffffffffu, incl, off);
        if (lane >= off) incl += t;
    }
    if (lane == 31) wsum[wid] = incl;
    __syncthreads();
    if (wid == 0) {
        int t = wsum[lane];
        int si = t;
        #pragma unroll
        for (int off = 1; off < 32; off <<= 1) {
            int u = __shfl_up_sync(0xffffffffu, si, off);
            if (lane >= off) si += u;
        }
        woff[lane] = si - t;
        if (lane == 31) total_sh = si;
    }
    __syncthreads();
    int run = incl - s + woff[wid];
    #pragma unroll
    for (int j = 0; j < SCAN_PER; j++) {
        int i = base + j;
        if (i < N_NODES) {
            g_rowptr[i] = run;
            g_cursor[i] = run;
        }
        run += vals[j];
    }
    if (tid == 0) g_rowptr[N_NODES] = total_sh;
}

__global__ void scatter_kernel(const int* __restrict__ dst) {
    int i = blockIdx.x * blockDim.x + threadIdx.x;
    if (i < N_EDGES) {
        int p = atomicAdd(&g_cursor[dst[i]], 1);
        g_eids[p] = i;
    }
}

// ---------------- BF16 TC GEMM: cp.async + ldmatrix, persistent CTAs (2-stage, 64KB) ----------------
// A: row-major bf16 (pair-words [m][K/2]) ; B: k-major bf16 (pair-words [k][Nc/2]).
// Chunk = 64 k. A smem: 128 rows x 128B; B smem: 64 k-rows x 256B. XOR-(row&7) 16B-group swizzle.
// MODE 0: +bias (nullable)   MODE 1: relu(+bias)   MODE 2: +bias +res
#define BM 128
#define BN 128
#define GEMM_SMEM_BYTES 65536   // [A0|A1|B0|B1] x 16KB

__device__ __forceinline__ void cp_async16(uint32_t dst, const void* src, uint32_t sz) {
    asm volatile("cp.async.ca.shared.global [%0], [%1], 16, %2;"
                 :: "r"(dst), "l"(src), "r"(sz) : "memory");
}
__device__ __forceinline__ void cp_commit() {
    asm volatile("cp.async.commit_group;" ::: "memory");
}
__device__ __forceinline__ void cp_wait1() {
    asm volatile("cp.async.wait_group 1;" ::: "memory");
}
__device__ __forceinline__ void cp_wait0() {
    asm volatile("cp.async.wait_group 0;" ::: "memory");
}

__device__ __forceinline__ uint32_t smem_u32(const void* p) {
    uint32_t a;
    asm("{ .reg .u64 t; cvta.to.shared.u64 t, %1; cvt.u32.u64 %0, t; }" : "=r"(a) : "l"(p));
    return a;
}

#define LDMX4(r0, r1, r2, r3, addr) \
    asm volatile("ldmatrix.sync.aligned.m8n8.x4.shared.b16 {%0,%1,%2,%3}, [%4];" \
                 : "=r"(r0), "=r"(r1), "=r"(r2), "=r"(r3) : "r"(addr))

#define LDMX4T(r0, r1, r2, r3, addr) \
    asm volatile("ldmatrix.sync.aligned.m8n8.x4.trans.shared.b16 {%0,%1,%2,%3}, [%4];" \
                 : "=r"(r0), "=r"(r1), "=r"(r2), "=r"(r3) : "r"(addr))

__device__ __forceinline__ void mma_bf16(float4& c, const uint32_t a[4], const uint32_t b[2]) {
    asm volatile(
        "mma.sync.aligned.m16n8k16.row.col.f32.bf16.bf16.f32 "
        "{%0,%1,%2,%3}, {%4,%5,%6,%7}, {%8,%9}, {%0,%1,%2,%3};"
        : "+f"(c.x), "+f"(c.y), "+f"(c.z), "+f"(c.w)
        : "r"(a[0]), "r"(a[1]), "r"(a[2]), "r"(a[3]), "r"(b[0]), "r"(b[1]));
}

template <int MODE, bool OUTBF>
__device__ __forceinline__ void gemm_tile(
    uint32_t sbase,                        // smem byte base (cvta'd, 1KB aligned)
    int M, int K, int Nc, int m0, int n0,
    const uint32_t* __restrict__ Aw,       // [m][K/2]
    const uint32_t* __restrict__ Bw,       // [k][Nc/2]
    const float* __restrict__ bias,
    const float* __restrict__ res,
    float* __restrict__ C,
    uint32_t* __restrict__ Cbf)
{
    const int tid  = threadIdx.x;
    const int lane = tid & 31;
    const int warp = tid >> 5;
    const int g  = lane >> 2;
    const int tg = lane & 3;
    const int wm = (warp >> 2) * 64;
    const int wn = (warp & 3) * 32;

    const int Khalf = K >> 1;
    const int Nhalf = Nc >> 1;
    const int nch = K >> 6;                // 64-k chunks

    // ---- fill thread mapping ----
    const int fa_row = tid >> 1;           // 0..127
    const int fa_h0  = (tid & 1) * 4;      // group base 0/4
    const int fb_row = tid >> 2;           // 0..63 (k row within chunk)
    const int fb_h0  = (tid & 3) * 4;      // group base 0..12

    const int arow_g   = m0 + fa_row;
    const uint32_t asz = (arow_g < M) ? 16u : 0u;
    const uint32_t* aSrcRow = Aw + (size_t)((arow_g < M) ? arow_g : (M - 1)) * Khalf + fa_h0 * 4;
    const uint32_t aDst0 = sbase + fa_row * 128;
    const uint32_t* bSrcRow0 = Bw + (size_t)fb_row * Nhalf + (n0 >> 1) + fb_h0 * 4;
    const uint32_t bDst0 = sbase + 32768 + fb_row * 256;

    // ---- ldmatrix addresses (h=0 / ks=0), lane-static ----
    const int lr = lane & 7;
    const int mi = lane >> 3;
    const int hs = lane >> 4;              // 0/1 : k-half select for A
    uint32_t aAddr0[4];
    #pragma unroll
    for (int mt = 0; mt < 4; mt++) {
        int r = wm + mt * 16 + lr + (mi & 1) * 8;
        aAddr0[mt] = sbase + r * 128 + ((r & 7) << 4);
    }
    uint32_t bAddr0[2];
    #pragma unroll
    for (int np = 0; np < 2; np++) {
        int kR = (mi >> 1) * 8 + lr;                   // k row within k16
        int hB = (wn >> 3) + np * 2 + (mi & 1);        // n-group
        bAddr0[np] = sbase + 32768 + kR * 256 + ((hB ^ lr) << 4);
    }

    float4 acc[4][4];
    #pragma unroll
    for (int i = 0; i < 4; i++)
        #pragma unroll
        for (int j = 0; j < 4; j++) acc[i][j] = make_float4(0.f, 0.f, 0.f, 0.f);

    // ---- prologue: chunk 0 -> buffer 0 ----
    {
        #pragma unroll
        for (int j = 0; j < 4; j++) {
            int h = fa_h0 + j;
            cp_async16(aDst0 + ((h ^ (fa_row & 7)) << 4), aSrcRow + j * 4, asz);
        }
        #pragma unroll
        for (int j = 0; j < 4; j++) {
            int h = fb_h0 + j;
            cp_async16(bDst0 + ((h ^ (fb_row & 7)) << 4), bSrcRow0 + j * 4, 16u);
        }
        cp_commit();
    }

    for (int ch = 0; ch < nch; ch++) {
        const uint32_t abuf = (ch & 1) ? 16384u : 0u;
        const bool has_next = (ch + 1 < nch);

        if (has_next) {
            const uint32_t nbuf = 16384u - abuf;
            const int kw0 = (ch + 1) * 32;             // A words
            #pragma unroll
            for (int j = 0; j < 4; j++) {
                int h = fa_h0 + j;
                cp_async16(aDst0 + nbuf + ((h ^ (fa_row & 7)) << 4), aSrcRow + kw0 + j * 4, asz);
            }
            const size_t bk = (size_t)(ch + 1) * 64 * Nhalf;  // B k-row advance
            #pragma unroll
            for (int j = 0; j < 4; j++) {
                int h = fb_h0 + j;
                cp_async16(bDst0 + nbuf + ((h ^ (fb_row & 7)) << 4), bSrcRow0 + bk + j * 4, 16u);
            }
            cp_commit();
            cp_wait1();
        } else {
            cp_wait0();
        }
        __syncthreads();

        #pragma unroll
        for (int ks = 0; ks < 4; ks++) {
            uint32_t afr[4][4];
            uint32_t bfr[4][2];
            const uint32_t hxor = (uint32_t)((2 * ks + hs) << 4);
            #pragma unroll
            for (int mt = 0; mt < 4; mt++)
                LDMX4(afr[mt][0], afr[mt][1], afr[mt][2], afr[mt][3],
                      (aAddr0[mt] + abuf) ^ hxor);
            #pragma unroll
            for (int np = 0; np < 2; np++) {
                uint32_t r0, r1, r2, r3;
                LDMX4T(r0, r1, r2, r3, bAddr0[np] + abuf + ks * 4096);
                bfr[2 * np][0] = r0; bfr[2 * np][1] = r2;
                bfr[2 * np + 1][0] = r1; bfr[2 * np + 1][1] = r3;
            }
            #pragma unroll
            for (int mt = 0; mt < 4; mt++)
                #pragma unroll
                for (int nt = 0; nt < 4; nt++)
                    mma_bf16(acc[mt][nt], afr[mt], bfr[nt]);
        }
        __syncthreads();
    }

    // ---- epilogue ----
    #pragma unroll
    for (int mt = 0; mt < 4; mt++) {
        #pragma unroll
        for (int nt = 0; nt < 4; nt++) {
            const int row0 = m0 + wm + mt * 16 + g;
            const int row1 = row0 + 8;
            const int col  = n0 + wn + nt * 8 + tg * 2;
            float2 v0 = make_float2(acc[mt][nt].x, acc[mt][nt].y);
            float2 v1 = make_float2(acc[mt][nt].z, acc[mt][nt].w);
            if (bias) {
                float2 bb = *(const float2*)(bias + col);
                v0.x += bb.x; v0.y += bb.y;
                v1.x += bb.x; v1.y += bb.y;
            }
            if (MODE == 2) {
                if (row0 < M) {
                    float2 r0 = *(const float2*)(res + (size_t)row0 * Nc + col);
                    v0.x += r0.x; v0.y += r0.y;
                }
                if (row1 < M) {
                    float2 r1 = *(const float2*)(res + (size_t)row1 * Nc + col);
                    v1.x += r1.x; v1.y += r1.y;
                }
            }
            if (MODE == 1) {
                v0.x = fmaxf(v0.x, 0.f); v0.y = fmaxf(v0.y, 0.f);
                v1.x = fmaxf(v1.x, 0.f); v1.y = fmaxf(v1.y, 0.f);
            }
            if (OUTBF) {
                if (row0 < M) Cbf[(size_t)row0 * (Nc >> 1) + (col >> 1)] = packbf2(v0.x, v0.y);
                if (row1 < M) Cbf[(size_t)row1 * (Nc >> 1) + (col >> 1)] = packbf2(v1.x, v1.y);
            } else {
                if (row0 < M) *(float2*)(C + (size_t)row0 * Nc + col) = v0;
                if (row1 < M) *(float2*)(C + (size_t)row1 * Nc + col) = v1;
            }
        }
    }
}

template <int MODE, bool OUTBF>
__global__ __launch_bounds__(256, 2) void bf16_gemm_kernel(
    int M, int K, int Nc, int gn, int total_tiles,
    const uint32_t* __restrict__ Aw,
    const uint32_t* __restrict__ Bw,
    const float* __restrict__ bias,
    const float* __restrict__ res,
    float* __restrict__ C,
    uint32_t* __restrict__ Cbf)
{
    extern __shared__ __align__(1024) uint32_t dynsmem[];
    const uint32_t sbase = smem_u32(dynsmem);
    for (int t = blockIdx.x; t < total_tiles; t += gridDim.x) {
        const int m0 = (t / gn) * BM;
        const int n0 = (t % gn) * BN;
        gemm_tile<MODE, OUTBF>(sbase, M, K, Nc, m0, n0, Aw, Bw, bias, res, C, Cbf);
    }
}

// fused q/k/v: q -> fp32 ; k,v -> bf16 pair-words
__global__ __launch_bounds__(256, 2) void bf16_gemm_qkv_kernel(
    int M, int K, int Nc, int gn, int tiles_per,
    const uint32_t* __restrict__ Aw,
    const uint32_t* __restrict__ Bq,
    const uint32_t* __restrict__ Bk,
    const uint32_t* __restrict__ Bv,
    const float* __restrict__ biasq,
    float* __restrict__ Cq,
    uint32_t* __restrict__ Ckbf,
    uint32_t* __restrict__ Cvbf)
{
    extern __shared__ __align__(1024) uint32_t dynsmem[];
    const uint32_t sbase = smem_u32(dynsmem);
    const int total = 3 * tiles_per;
    for (int t = blockIdx.x; t < total; t += gridDim.x) {
        const int which = t / tiles_per;
        const int tt = t % tiles_per;
        const int m0 = (tt / gn) * BM;
        const int n0 = (tt % gn) * BN;
        if (which == 0) {
            gemm_tile<0, false>(sbase, M, K, Nc, m0, n0, Aw, Bq, biasq, nullptr, Cq, nullptr);
        } else if (which == 1) {
            gemm_tile<0, true>(sbase, M, K, Nc, m0, n0, Aw, Bk, nullptr, nullptr, nullptr, Ckbf);
        } else {
            gemm_tile<0, true>(sbase, M, K, Nc, m0, n0, Aw, Bv, nullptr, nullptr, nullptr, Cvbf);
        }
    }
}

// ---------------- edge aggregation: one warp per destination node ----------------
// q,rel fp32 ; k,v gathered as bf16 pair-words (uint4 per lane each). Pipelined depth-2.
__global__ void edge_agg_kernel(const float* __restrict__ rel,
                                const int* __restrict__ edge_feat,
                                const int* __restrict__ src)
{
    int gw = (blockIdx.x * blockDim.x + threadIdx.x) >> 5;
    int lane = threadIdx.x & 31;
    if (gw >= N_NODES) return;

    const float4* qr = (const float4*)(g_q + (size_t)gw * HS);
    float4 q0 = qr[2 * lane], q1 = qr[2 * lane + 1];

    float4 a0 = make_float4(0.f, 0.f, 0.f, 0.f);
    float4 a1 = make_float4(0.f, 0.f, 0.f, 0.f);
    float zsum = 0.f;

    const int beg = g_rowptr[gw], end = g_rowptr[gw + 1];
    const int ecol = 2 * (lane & 3);
    const float invs = 0.17677669529663687f;  // 1/sqrt(32)

    for (int base = beg; base < end; base += 32) {
        const int cnt = min(32, end - base);
        int s_l = 0, r_l = 0;
        if (base + lane < end) {
            int e = g_eids[base + lane];
            s_l = __ldg(&src[e]);
            r_l = __ldg(&edge_feat[e]);
        }

        int s_c = __shfl_sync(0xffffffffu, s_l, 0);
        int r_c = __shfl_sync(0xffffffffu, r_l, 0);
        const float4* er = (const float4*)(rel + (size_t)r_c * DK);
        uint4  kw = *(const uint4*)(g_kbf + (size_t)s_c * (HS / 2) + 4 * lane);
        uint4  vw = *(const uint4*)(g_vbf + (size_t)s_c * (HS / 2) + 4 * lane);
        float4 e0 = er[ecol],     e1 = er[ecol + 1];

        for (int j = 0; j < cnt; j++) {
            uint4  KW = kw, VW = vw;
            float4 E0 = e0, E1 = e1;
            if (j + 1 < cnt) {
                int s_n = __shfl_sync(0xffffffffu, s_l, j + 1);
                int r_n = __shfl_sync(0xffffffffu, r_l, j + 1);
                const float4* ern = (const float4*)(rel + (size_t)r_n * DK);
                kw = *(const uint4*)(g_kbf + (size_t)s_n * (HS / 2) + 4 * lane);
                vw = *(const uint4*)(g_vbf + (size_t)s_n * (HS / 2) + 4 * lane);
                e0 = ern[ecol];     e1 = ern[ecol + 1];
            }

            float2 k0 = unpackbf2(KW.x), k1 = unpackbf2(KW.y);
            float2 k2 = unpackbf2(KW.z), k3 = unpackbf2(KW.w);
            float d = (k0.x + E0.x) * q0.x + (k0.y + E0.y) * q0.y
                    + (k1.x + E0.z) * q0.z + (k1.y + E0.w) * q0.w
                    + (k2.x + E1.x) * q1.x + (k2.y + E1.y) * q1.y
                    + (k3.x + E1.z) * q1.z + (k3.y + E1.w) * q1.w;
            d += __shfl_xor_sync(0xffffffffu, d, 1);
            d += __shfl_xor_sync(0xffffffffu, d, 2);
            float sc = __expf(fminf(fmaxf(d * invs, -10.f), 10.f));

            float2 p0 = unpackbf2(VW.x), p1 = unpackbf2(VW.y);
            float2 p2 = unpackbf2(VW.z), p3 = unpackbf2(VW.w);
            a0.x += (p0.x + E0.x) * sc; a0.y += (p0.y + E0.y) * sc;
            a0.z += (p1.x + E0.z) * sc; a0.w += (p1.y + E0.w) * sc;
            a1.x += (p2.x + E1.x) * sc; a1.y += (p2.y + E1.y) * sc;
            a1.z += (p3.x + E1.z) * sc; a1.w += (p3.y + E1.w) * sc;
            zsum += sc;
        }
    }

    float inv = 1.f / zsum;
    uint4 w;
    w.x = packbf2(a0.x * inv, a0.y * inv);
    w.y = packbf2(a0.z * inv, a0.w * inv);
    w.z = packbf2(a1.x * inv, a1.y * inv);
    w.w = packbf2(a1.z * inv, a1.w * inv);
    *(uint4*)(g_obf + (size_t)gw * (HS / 2) + 4 * lane) = w;
}

// ---------------- layernorm: one warp per row; optional bf16 dual-write ----------------
__global__ void ln_kernel(const float* __restrict__ in,
                          const float* __restrict__ gamma,
                          const float* __restrict__ beta,
                          float* __restrict__ out,
                          uint32_t* __restrict__ outbf)
{
    int gw = (blockIdx.x * blockDim.x + threadIdx.x) >> 5;
    int lane = threadIdx.x & 31;
    if (gw >= N_NODES) return;

    const float4* row = (const float4*)(in + (size_t)gw * HS);
    float4 x0 = row[2 * lane], x1 = row[2 * lane + 1];

    float s = x0.x + x0.y + x0.z + x0.w + x1.x + x1.y + x1.z + x1.w;
    #pragma unroll
    for (int off = 16; off; off >>= 1) s += __shfl_xor_sync(0xffffffffu, s, off);
    float mean = s * (1.f / HS);

    float d0 = x0.x - mean, d1 = x0.y - mean, d2 = x0.z - mean, d3 = x0.w - mean;
    float d4 = x1.x - mean, d5 = x1.y - mean, d6 = x1.z - mean, d7 = x1.w - mean;
    float ss = d0 * d0 + d1 * d1 + d2 * d2 + d3 * d3 + d4 * d4 + d5 * d5 + d6 * d6 + d7 * d7;
    #pragma unroll
    for (int off = 16; off; off >>= 1) ss += __shfl_xor_sync(0xffffffffu, ss, off);
    float rstd = rsqrtf(ss * (1.f / HS) + 1e-5f);

    const float4* gr = (const float4*)gamma;
    const float4* br = (const float4*)beta;
    float4 gg0 = gr[2 * lane], gg1 = gr[2 * lane + 1];
    float4 bb0 = br[2 * lane], bb1 = br[2 * lane + 1];

    float o0 = d0 * rstd * gg0.x + bb0.x;
    float o1 = d1 * rstd * gg0.y + bb0.y;
    float o2 = d2 * rstd * gg0.z + bb0.z;
    float o3 = d3 * rstd * gg0.w + bb0.w;
    float o4 = d4 * rstd * gg1.x + bb1.x;
    float o5 = d5 * rstd * gg1.y + bb1.y;
    float o6 = d6 * rstd * gg1.z + bb1.z;
    float o7 = d7 * rstd * gg1.w + bb1.w;

    float4* orow = (float4*)(out + (size_t)gw * HS);
    orow[2 * lane]     = make_float4(o0, o1, o2, o3);
    orow[2 * lane + 1] = make_float4(o4, o5, o6, o7);

    if (outbf) {
        uint4 w;
        w.x = packbf2(o0, o1); w.y = packbf2(o2, o3);
        w.z = packbf2(o4, o5); w.w = packbf2(o6, o7);
        *(uint4*)(outbf + (size_t)gw * (HS / 2) + 4 * lane) = w;
    }
}

// ---------------- host orchestration ----------------
extern "C" void kernel_launch(void* const* d_in, const int* in_sizes, int n_in,
                              void* d_out, int out_size)
{
    const float* x_in     = (const float*)d_in[0];
    const int*   edge_feat= (const int*)  d_in[1];
    const int*   src      = (const int*)  d_in[2];
    const int*   dst      = (const int*)  d_in[3];
    const float* rel      = (const float*)d_in[4];
    const float* Wq       = (const float*)d_in[5];
    const float* bq       = (const float*)d_in[6];
    const float* Wk       = (const float*)d_in[7];
    const float* Wv       = (const float*)d_in[8];
    const float* Wo       = (const float*)d_in[9];
    const float* bo       = (const float*)d_in[10];
    const float* W1       = (const float*)d_in[11];
    const float* b1       = (const float*)d_in[12];
    const float* W2       = (const float*)d_in[13];
    const float* b2       = (const float*)d_in[14];
    const float* ln1g     = (const float*)d_in[15];
    const float* ln1b     = (const float*)d_in[16];
    const float* ln2g     = (const float*)d_in[17];
    const float* ln2b     = (const float*)d_in[18];

    float *q, *tmp, *h, *xbuf;
    uint32_t *xbf, *kbf, *vbf, *obf, *hbf, *ffbf, *wbf;
    int* cnt;
    cudaGetSymbolAddress((void**)&q,    g_q);
    cudaGetSymbolAddress((void**)&tmp,  g_tmp);
    cudaGetSymbolAddress((void**)&h,    g_h);
    cudaGetSymbolAddress((void**)&xbuf, g_xbuf);
    cudaGetSymbolAddress((void**)&xbf,  g_xbf);
    cudaGetSymbolAddress((void**)&kbf,  g_kbf);
    cudaGetSymbolAddress((void**)&vbf,  g_vbf);
    cudaGetSymbolAddress((void**)&obf,  g_obf);
    cudaGetSymbolAddress((void**)&hbf,  g_hbf);
    cudaGetSymbolAddress((void**)&ffbf, g_ffbf);
    cudaGetSymbolAddress((void**)&wbf,  g_wbf);
    cudaGetSymbolAddress((void**)&cnt,  g_cnt);

    // opt-in to 64KB dynamic smem (idempotent; not a stream op)
    cudaFuncSetAttribute(bf16_gemm_qkv_kernel,
                         cudaFuncAttributeMaxDynamicSharedMemorySize, GEMM_SMEM_BYTES);
    cudaFuncSetAttribute(bf16_gemm_kernel<2, false>,
                         cudaFuncAttributeMaxDynamicSharedMemorySize, GEMM_SMEM_BYTES);
    cudaFuncSetAttribute(bf16_gemm_kernel<1, true>,
                         cudaFuncAttributeMaxDynamicSharedMemorySize, GEMM_SMEM_BYTES);

    // CSR + conversions
    cudaMemsetAsync(cnt, 0, N_NODES * sizeof(int));
    const int prep_items = NXW + 2 * WL_STRIDE + N_EDGES;
    prep_kernel<<<(prep_items + 255) / 256, 256>>>(x_in, Wq, Wk, Wv, Wo, W1, W2, dst);
    scan_kernel<<<1, 1024>>>();
    scatter_kernel<<<(N_EDGES + 255) / 256, 256>>>(dst);

    const int warp_blocks = (N_NODES * 32 + 255) / 256;
    const int GM = (N_NODES + BM - 1) / BM;   // 157
    const int gnHS = HS / BN;                  // 2
    const int gnFF = FF_DIM / BN;              // 8
    const int tilesHS = GM * gnHS;             // 314
    const int tilesFF = GM * gnFF;             // 1256
    const int PGRID = 296;

    const float* xres = x_in;
    for (int l = 0; l < N_LAYERS; l++) {
        const uint32_t* wl = wbf + (size_t)l * WL_STRIDE;

        bf16_gemm_qkv_kernel<<<PGRID, 256, GEMM_SMEM_BYTES>>>(
            N_NODES, HS, HS, gnHS, tilesHS,
            xbf, wl + WQ_OFF, wl + WK_OFF, wl + WV_OFF,
            bq + l * HS, q, kbf, vbf);

        edge_agg_kernel<<<warp_blocks, 256>>>(rel, edge_feat, src);

        bf16_gemm_kernel<2, false><<<PGRID, 256, GEMM_SMEM_BYTES>>>(
            N_NODES, HS, HS, gnHS, tilesHS,
            obf, wl + WO_OFF, bo + l * HS, xres, tmp, nullptr);
        ln_kernel<<<warp_blocks, 256>>>(tmp, ln1g + l * HS, ln1b + l * HS, h, hbf);

        bf16_gemm_kernel<1, true><<<PGRID, 256, GEMM_SMEM_BYTES>>>(
            N_NODES, HS, FF_DIM, gnFF, tilesFF,
            hbf, wl + W1_OFF, b1 + l * FF_DIM, nullptr, nullptr, ffbf);
        bf16_gemm_kernel<2, false><<<PGRID, 256, GEMM_SMEM_BYTES>>>(
            N_NODES, FF_DIM, HS, gnHS, tilesHS,
            ffbf, wl + W2_OFF, b2 + l * HS, h, tmp, nullptr);

        if (l == N_LAYERS - 1) {
            ln_kernel<<<warp_blocks, 256>>>(tmp, ln2g + l * HS, ln2b + l * HS, (float*)d_out, nullptr);
        } else {
            ln_kernel<<<warp_blocks, 256>>>(tmp, ln2g + l * HS, ln2b + l * HS, xbuf, xbf);
            xres = xbuf;
        }
    }
}

// round 16
// speedup vs baseline: 1.0333x; 1.0295x over previous
#include <cuda_runtime.h>
#include <cuda_bf16.h>
#include <cstdint>

#define N_NODES 20000
#define N_EDGES 640000
#define HS 256
#define H_HEADS 8
#define DK 32
#define FF_DIM 1024
#define N_LAYERS 2

// ---------------- scratch (static device globals; no runtime alloc) ----------------
__device__ float g_q[(size_t)N_NODES * HS];
__device__ float g_k[(size_t)N_NODES * HS];
__device__ float g_tmp[(size_t)N_NODES * HS];
__device__ float g_h[(size_t)N_NODES * HS];
__device__ float g_xbuf[(size_t)N_NODES * HS];

// bf16 pair-word activation buffers: word i = {val[2i], val[2i+1]} (row-major bf16)
__device__ __align__(16) uint32_t g_xbf[(size_t)N_NODES * HS / 2];
__device__ __align__(16) uint32_t g_vbf[(size_t)N_NODES * HS / 2];
__device__ __align__(16) uint32_t g_obf[(size_t)N_NODES * HS / 2];
__device__ __align__(16) uint32_t g_hbf[(size_t)N_NODES * HS / 2];
__device__ __align__(16) uint32_t g_ffbf[(size_t)N_NODES * FF_DIM / 2];

// k-major bf16 weights: word(k, n2) = {W[k][2*n2], W[k][2*n2+1]} at [k * Nc/2 + n2]
#define WQ_OFF 0
#define WK_OFF 32768
#define WV_OFF 65536
#define WO_OFF 98304
#define W1_OFF 131072
#define W2_OFF 262144
#define WL_STRIDE 393216
__device__ __align__(16) uint32_t g_wbf[2 * WL_STRIDE];

__device__ int g_cnt[N_NODES];
__device__ int g_rowptr[N_NODES + 1];
__device__ int g_cursor[N_NODES];
__device__ int g_eids[N_EDGES];

__device__ __forceinline__ uint32_t packbf2(float lo, float hi) {
    __nv_bfloat162 h = __float22bfloat162_rn(make_float2(lo, hi));
    return *reinterpret_cast<uint32_t*>(&h);
}

__device__ __forceinline__ float2 unpackbf2(uint32_t w) {
    return __bfloat1622float2(*reinterpret_cast<__nv_bfloat162*>(&w));
}

// ---------------- operand conversion ----------------
__global__ void convert_weights_kernel(const float* __restrict__ Wq, const float* __restrict__ Wk,
                                       const float* __restrict__ Wv, const float* __restrict__ Wo,
                                       const float* __restrict__ W1, const float* __restrict__ W2) {
    int w = blockIdx.x * blockDim.x + threadIdx.x;
    if (w >= 2 * WL_STRIDE) return;
    int layer = w / WL_STRIDE;
    int r = w % WL_STRIDE;
    const float* src;
    int kk, n2, Nc;
    if (r < W1_OFF) {
        int m = r >> 15; int rr = r & 32767; Nc = HS;
        kk = rr >> 7; n2 = rr & 127;
        src = (m == 0 ? Wq : m == 1 ? Wk : m == 2 ? Wv : Wo) + (size_t)layer * HS * HS;
    } else if (r < W2_OFF) {
        int rr = r - W1_OFF; Nc = FF_DIM;
        kk = rr >> 9; n2 = rr & 511;
        src = W1 + (size_t)layer * HS * FF_DIM;
    } else {
        int rr = r - W2_OFF; Nc = HS;
        kk = rr >> 7; n2 = rr & 127;
        src = W2 + (size_t)layer * FF_DIM * HS;
    }
    const float* p = src + (size_t)kk * Nc + 2 * n2;
    g_wbf[w] = packbf2(p[0], p[1]);
}

__global__ void convert_x_kernel(const float* __restrict__ x) {
    int i = blockIdx.x * blockDim.x + threadIdx.x;
    if (i < N_NODES * HS / 2) g_xbf[i] = packbf2(x[2 * i], x[2 * i + 1]);
}

// ---------------- CSR build ----------------
__global__ void hist_kernel(const int* __restrict__ dst) {
    int i = blockIdx.x * blockDim.x + threadIdx.x;
    if (i < N_EDGES) atomicAdd(&g_cnt[dst[i]], 1);
}

// single-pass scan: 1024 threads x 20 serial elems, 3 barriers
#define SCAN_PER 20
__global__ void scan_kernel() {
    __shared__ int wsum[32];
    __shared__ int woff[32];
    __shared__ int total_sh;
    const int tid = threadIdx.x, lane = tid & 31, wid = tid >> 5;
    const int base = tid * SCAN_PER;

    int vals[SCAN_PER];
    int s = 0;
    #pragma unroll
    for (int j = 0; j < SCAN_PER; j++) {
        int i = base + j;
        int v = (i < N_NODES) ? g_cnt[i] : 0;
        vals[j] = v; s += v;
    }
    int incl = s;
    #pragma unroll
    for (int off = 1; off < 32; off <<= 1) {
        int t = __shfl_up_sync(0xffffffffu, incl, off);
        if (lane >= off) incl += t;
    }
    if (lane == 31) wsum[wid] = incl;
    __syncthreads();
    if (wid == 0) {
        int t = wsum[lane];
        int si = t;
        #pragma unroll
        for (int off = 1; off < 32; off <<= 1) {
            int u = __shfl_up_sync(0xffffffffu, si, off);
            if (lane >= off) si += u;
        }
        woff[lane] = si - t;
        if (lane == 31) total_sh = si;
    }
    __syncthreads();
    int run = incl - s + woff[wid];
    #pragma unroll
    for (int j = 0; j < SCAN_PER; j++) {
        int i = base + j;
        if (i < N_NODES) {
            g_rowptr[i] = run;
            g_cursor[i] = run;
        }
        run += vals[j];
    }
    if (tid == 0) g_rowptr[N_NODES] = total_sh;
}

__global__ void scatter_kernel(const int* __restrict__ dst) {
    int i = blockIdx.x * blockDim.x + threadIdx.x;
    if (i < N_EDGES) {
        int p = atomicAdd(&g_cursor[dst[i]], 1);
        g_eids[p] = i;
    }
}

// ---------------- BF16 TC GEMM: cp.async + ldmatrix, persistent CTAs (2-stage, 64KB) ----------------
// A: row-major bf16 (pair-words [m][K/2]) ; B: k-major bf16 (pair-words [k][Nc/2]).
// Chunk = 64 k. A smem: 128 rows x 128B; B smem: 64 k-rows x 256B. XOR-(row&7) 16B-group swizzle.
// MODE 0: +bias (nullable)   MODE 1: relu(+bias)   MODE 2: +bias +res
#define BM 128
#define BN 128
#define GEMM_SMEM_BYTES 65536   // [A0|A1|B0|B1] x 16KB

__device__ __forceinline__ void cp_async16(uint32_t dst, const void* src, uint32_t sz) {
    asm volatile("cp.async.ca.shared.global [%0], [%1], 16, %2;"
                 :: "r"(dst), "l"(src), "r"(sz) : "memory");
}
__device__ __forceinline__ void cp_commit() {
    asm volatile("cp.async.commit_group;" ::: "memory");
}
__device__ __forceinline__ void cp_wait1() {
    asm volatile("cp.async.wait_group 1;" ::: "memory");
}
__device__ __forceinline__ void cp_wait0() {
    asm volatile("cp.async.wait_group 0;" ::: "memory");
}

__device__ __forceinline__ uint32_t smem_u32(const void* p) {
    uint32_t a;
    asm("{ .reg .u64 t; cvta.to.shared.u64 t, %1; cvt.u32.u64 %0, t; }" : "=r"(a) : "l"(p));
    return a;
}

#define LDMX4(r0, r1, r2, r3, addr) \
    asm volatile("ldmatrix.sync.aligned.m8n8.x4.shared.b16 {%0,%1,%2,%3}, [%4];" \
                 : "=r"(r0), "=r"(r1), "=r"(r2), "=r"(r3) : "r"(addr))

#define LDMX4T(r0, r1, r2, r3, addr) \
    asm volatile("ldmatrix.sync.aligned.m8n8.x4.trans.shared.b16 {%0,%1,%2,%3}, [%4];" \
                 : "=r"(r0), "=r"(r1), "=r"(r2), "=r"(r3) : "r"(addr))

__device__ __forceinline__ void mma_bf16(float4& c, const uint32_t a[4], const uint32_t b[2]) {
    asm volatile(
        "mma.sync.aligned.m16n8k16.row.col.f32.bf16.bf16.f32 "
        "{%0,%1,%2,%3}, {%4,%5,%6,%7}, {%8,%9}, {%0,%1,%2,%3};"
        : "+f"(c.x), "+f"(c.y), "+f"(c.z), "+f"(c.w)
        : "r"(a[0]), "r"(a[1]), "r"(a[2]), "r"(a[3]), "r"(b[0]), "r"(b[1]));
}

template <int MODE, bool OUTBF>
__device__ __forceinline__ void gemm_tile(
    uint32_t sbase,
    int M, int K, int Nc, int m0, int n0,
    const uint32_t* __restrict__ Aw,
    const uint32_t* __restrict__ Bw,
    const float* __restrict__ bias,
    const float* __restrict__ res,
    float* __restrict__ C,
    uint32_t* __restrict__ Cbf)
{
    const int tid  = threadIdx.x;
    const int lane = tid & 31;
    const int warp = tid >> 5;
    const int g  = lane >> 2;
    const int tg = lane & 3;
    const int wm = (warp >> 2) * 64;
    const int wn = (warp & 3) * 32;

    const int Khalf = K >> 1;
    const int Nhalf = Nc >> 1;
    const int nch = K >> 6;

    const int fa_row = tid >> 1;
    const int fa_h0  = (tid & 1) * 4;
    const int fb_row = tid >> 2;
    const int fb_h0  = (tid & 3) * 4;

    const int arow_g   = m0 + fa_row;
    const uint32_t asz = (arow_g < M) ? 16u : 0u;
    const uint32_t* aSrcRow = Aw + (size_t)((arow_g < M) ? arow_g : (M - 1)) * Khalf + fa_h0 * 4;
    const uint32_t aDst0 = sbase + fa_row * 128;
    const uint32_t* bSrcRow0 = Bw + (size_t)fb_row * Nhalf + (n0 >> 1) + fb_h0 * 4;
    const uint32_t bDst0 = sbase + 32768 + fb_row * 256;

    const int lr = lane & 7;
    const int mi = lane >> 3;
    const int hs = lane >> 4;
    uint32_t aAddr0[4];
    #pragma unroll
    for (int mt = 0; mt < 4; mt++) {
        int r = wm + mt * 16 + lr + (mi & 1) * 8;
        aAddr0[mt] = sbase + r * 128 + ((r & 7) << 4);
    }
    uint32_t bAddr0[2];
    #pragma unroll
    for (int np = 0; np < 2; np++) {
        int kR = (mi >> 1) * 8 + lr;
        int hB = (wn >> 3) + np * 2 + (mi & 1);
        bAddr0[np] = sbase + 32768 + kR * 256 + ((hB ^ lr) << 4);
    }

    float4 acc[4][4];
    #pragma unroll
    for (int i = 0; i < 4; i++)
        #pragma unroll
        for (int j = 0; j < 4; j++) acc[i][j] = make_float4(0.f, 0.f, 0.f, 0.f);

    {
        #pragma unroll
        for (int j = 0; j < 4; j++) {
            int h = fa_h0 + j;
            cp_async16(aDst0 + ((h ^ (fa_row & 7)) << 4), aSrcRow + j * 4, asz);
        }
        #pragma unroll
        for (int j = 0; j < 4; j++) {
            int h = fb_h0 + j;
            cp_async16(bDst0 + ((h ^ (fb_row & 7)) << 4), bSrcRow0 + j * 4, 16u);
        }
        cp_commit();
    }

    for (int ch = 0; ch < nch; ch++) {
        const uint32_t abuf = (ch & 1) ? 16384u : 0u;
        const bool has_next = (ch + 1 < nch);

        if (has_next) {
            const uint32_t nbuf = 16384u - abuf;
            const int kw0 = (ch + 1) * 32;
            #pragma unroll
            for (int j = 0; j < 4; j++) {
                int h = fa_h0 + j;
                cp_async16(aDst0 + nbuf + ((h ^ (fa_row & 7)) << 4), aSrcRow + kw0 + j * 4, asz);
            }
            const size_t bk = (size_t)(ch + 1) * 64 * Nhalf;
            #pragma unroll
            for (int j = 0; j < 4; j++) {
                int h = fb_h0 + j;
                cp_async16(bDst0 + nbuf + ((h ^ (fb_row & 7)) << 4), bSrcRow0 + bk + j * 4, 16u);
            }
            cp_commit();
            cp_wait1();
        } else {
            cp_wait0();
        }
        __syncthreads();

        #pragma unroll
        for (int ks = 0; ks < 4; ks++) {
            uint32_t afr[4][4];
            uint32_t bfr[4][2];
            const uint32_t hxor = (uint32_t)((2 * ks + hs) << 4);
            #pragma unroll
            for (int mt = 0; mt < 4; mt++)
                LDMX4(afr[mt][0], afr[mt][1], afr[mt][2], afr[mt][3],
                      (aAddr0[mt] + abuf) ^ hxor);
            #pragma unroll
            for (int np = 0; np < 2; np++) {
                uint32_t r0, r1, r2, r3;
                LDMX4T(r0, r1, r2, r3, bAddr0[np] + abuf + ks * 4096);
                bfr[2 * np][0] = r0; bfr[2 * np][1] = r2;
                bfr[2 * np + 1][0] = r1; bfr[2 * np + 1][1] = r3;
            }
            #pragma unroll
            for (int mt = 0; mt < 4; mt++)
                #pragma unroll
                for (int nt = 0; nt < 4; nt++)
                    mma_bf16(acc[mt][nt], afr[mt], bfr[nt]);
        }
        __syncthreads();
    }

    #pragma unroll
    for (int mt = 0; mt < 4; mt++) {
        #pragma unroll
        for (int nt = 0; nt < 4; nt++) {
            const int row0 = m0 + wm + mt * 16 + g;
            const int row1 = row0 + 8;
            const int col  = n0 + wn + nt * 8 + tg * 2;
            float2 v0 = make_float2(acc[mt][nt].x, acc[mt][nt].y);
            float2 v1 = make_float2(acc[mt][nt].z, acc[mt][nt].w);
            if (bias) {
                float2 bb = *(const float2*)(bias + col);
                v0.x += bb.x; v0.y += bb.y;
                v1.x += bb.x; v1.y += bb.y;
            }
            if (MODE == 2) {
                if (row0 < M) {
                    float2 r0 = *(const float2*)(res + (size_t)row0 * Nc + col);
                    v0.x += r0.x; v0.y += r0.y;
                }
                if (row1 < M) {
                    float2 r1 = *(const float2*)(res + (size_t)row1 * Nc + col);
                    v1.x += r1.x; v1.y += r1.y;
                }
            }
            if (MODE == 1) {
                v0.x = fmaxf(v0.x, 0.f); v0.y = fmaxf(v0.y, 0.f);
                v1.x = fmaxf(v1.x, 0.f); v1.y = fmaxf(v1.y, 0.f);
            }
            if (OUTBF) {
                if (row0 < M) Cbf[(size_t)row0 * (Nc >> 1) + (col >> 1)] = packbf2(v0.x, v0.y);
                if (row1 < M) Cbf[(size_t)row1 * (Nc >> 1) + (col >> 1)] = packbf2(v1.x, v1.y);
            } else {
                if (row0 < M) *(float2*)(C + (size_t)row0 * Nc + col) = v0;
                if (row1 < M) *(float2*)(C + (size_t)row1 * Nc + col) = v1;
            }
        }
    }
}

template <int MODE, bool OUTBF>
__global__ __launch_bounds__(256, 2) void bf16_gemm_kernel(
    int M, int K, int Nc, int gn, int total_tiles,
    const uint32_t* __restrict__ Aw,
    const uint32_t* __restrict__ Bw,
    const float* __restrict__ bias,
    const float* __restrict__ res,
    float* __restrict__ C,
    uint32_t* __restrict__ Cbf)
{
    extern __shared__ __align__(1024) uint32_t dynsmem[];
    const uint32_t sbase = smem_u32(dynsmem);
    for (int t = blockIdx.x; t < total_tiles; t += gridDim.x) {
        const int m0 = (t / gn) * BM;
        const int n0 = (t % gn) * BN;
        gemm_tile<MODE, OUTBF>(sbase, M, K, Nc, m0, n0, Aw, Bw, bias, res, C, Cbf);
    }
}

// fused q/k/v: q,k -> fp32 ; v -> bf16 pair-words
__global__ __launch_bounds__(256, 2) void bf16_gemm_qkv_kernel(
    int M, int K, int Nc, int gn, int tiles_per,
    const uint32_t* __restrict__ Aw,
    const uint32_t* __restrict__ Bq,
    const uint32_t* __restrict__ Bk,
    const uint32_t* __restrict__ Bv,
    const float* __restrict__ biasq,
    float* __restrict__ Cq,
    float* __restrict__ Ck,
    uint32_t* __restrict__ Cvbf)
{
    extern __shared__ __align__(1024) uint32_t dynsmem[];
    const uint32_t sbase = smem_u32(dynsmem);
    const int total = 3 * tiles_per;
    for (int t = blockIdx.x; t < total; t += gridDim.x) {
        const int which = t / tiles_per;
        const int tt = t % tiles_per;
        const int m0 = (tt / gn) * BM;
        const int n0 = (tt % gn) * BN;
        if (which == 2) {
            gemm_tile<0, true>(sbase, M, K, Nc, m0, n0, Aw, Bv, nullptr, nullptr, nullptr, Cvbf);
        } else {
            const uint32_t* B = (which == 0) ? Bq : Bk;
            float* C          = (which == 0) ? Cq : Ck;
            const float* bias = (which == 0) ? biasq : nullptr;
            gemm_tile<0, false>(sbase, M, K, Nc, m0, n0, Aw, B, bias, nullptr, C, nullptr);
        }
    }
}

// ---------------- edge aggregation: one warp per destination node ----------------
// q,k,rel fp32 ; v gathered as bf16 pair-words. Pipelined depth-2.
__global__ void edge_agg_kernel(const float* __restrict__ rel,
                                const int* __restrict__ edge_feat,
                                const int* __restrict__ src)
{
    int gw = (blockIdx.x * blockDim.x + threadIdx.x) >> 5;
    int lane = threadIdx.x & 31;
    if (gw >= N_NODES) return;

    const float4* qr = (const float4*)(g_q + (size_t)gw * HS);
    float4 q0 = qr[2 * lane], q1 = qr[2 * lane + 1];

    float4 a0 = make_float4(0.f, 0.f, 0.f, 0.f);
    float4 a1 = make_float4(0.f, 0.f, 0.f, 0.f);
    float zsum = 0.f;

    const int beg = g_rowptr[gw], end = g_rowptr[gw + 1];
    const int ecol = 2 * (lane & 3);
    const float invs = 0.17677669529663687f;  // 1/sqrt(32)

    for (int base = beg; base < end; base += 32) {
        const int cnt = min(32, end - base);
        int s_l = 0, r_l = 0;
        if (base + lane < end) {
            int e = g_eids[base + lane];
            s_l = __ldg(&src[e]);
            r_l = __ldg(&edge_feat[e]);
        }

        int s_c = __shfl_sync(0xffffffffu, s_l, 0);
        int r_c = __shfl_sync(0xffffffffu, r_l, 0);
        const float4* kr = (const float4*)(g_k + (size_t)s_c * HS);
        const float4* er = (const float4*)(rel + (size_t)r_c * DK);
        float4 k0 = kr[2 * lane], k1 = kr[2 * lane + 1];
        uint4  vw = *(const uint4*)(g_vbf + (size_t)s_c * (HS / 2) + 4 * lane);
        float4 e0 = er[ecol],     e1 = er[ecol + 1];

        for (int j = 0; j < cnt; j++) {
            float4 K0 = k0, K1 = k1, E0 = e0, E1 = e1;
            uint4  VW = vw;
            if (j + 1 < cnt) {
                int s_n = __shfl_sync(0xffffffffu, s_l, j + 1);
                int r_n = __shfl_sync(0xffffffffu, r_l, j + 1);
                const float4* krn = (const float4*)(g_k + (size_t)s_n * HS);
                const float4* ern = (const float4*)(rel + (size_t)r_n * DK);
                k0 = krn[2 * lane]; k1 = krn[2 * lane + 1];
                vw = *(const uint4*)(g_vbf + (size_t)s_n * (HS / 2) + 4 * lane);
                e0 = ern[ecol];     e1 = ern[ecol + 1];
            }

            float d = (K0.x + E0.x) * q0.x + (K0.y + E0.y) * q0.y
                    + (K0.z + E0.z) * q0.z + (K0.w + E0.w) * q0.w
                    + (K1.x + E1.x) * q1.x + (K1.y + E1.y) * q1.y
                    + (K1.z + E1.z) * q1.z + (K1.w + E1.w) * q1.w;
            d += __shfl_xor_sync(0xffffffffu, d, 1);
            d += __shfl_xor_sync(0xffffffffu, d, 2);
            float sc = __expf(fminf(fmaxf(d * invs, -10.f), 10.f));

            float2 p0 = unpackbf2(VW.x), p1 = unpackbf2(VW.y);
            float2 p2 = unpackbf2(VW.z), p3 = unpackbf2(VW.w);
            a0.x += (p0.x + E0.x) * sc; a0.y += (p0.y + E0.y) * sc;
            a0.z += (p1.x + E0.z) * sc; a0.w += (p1.y + E0.w) * sc;
            a1.x += (p2.x + E1.x) * sc; a1.y += (p2.y + E1.y) * sc;
            a1.z += (p3.x + E1.z) * sc; a1.w += (p3.y + E1.w) * sc;
            zsum += sc;
        }
    }

    float inv = 1.f / zsum;
    uint4 w;
    w.x = packbf2(a0.x * inv, a0.y * inv);
    w.y = packbf2(a0.z * inv, a0.w * inv);
    w.z = packbf2(a1.x * inv, a1.y * inv);
    w.w = packbf2(a1.z * inv, a1.w * inv);
    *(uint4*)(g_obf + (size_t)gw * (HS / 2) + 4 * lane) = w;
}

// ---------------- layernorm: one warp per row; optional bf16 dual-write ----------------
__global__ void ln_kernel(const float* __restrict__ in,
                          const float* __restrict__ gamma,
                          const float* __restrict__ beta,
                          float* __restrict__ out,
                          uint32_t* __restrict__ outbf)
{
    int gw = (blockIdx.x * blockDim.x + threadIdx.x) >> 5;
    int lane = threadIdx.x & 31;
    if (gw >= N_NODES) return;

    const float4* row = (const float4*)(in + (size_t)gw * HS);
    float4 x0 = row[2 * lane], x1 = row[2 * lane + 1];

    float s = x0.x + x0.y + x0.z + x0.w + x1.x + x1.y + x1.z + x1.w;
    #pragma unroll
    for (int off = 16; off; off >>= 1) s += __shfl_xor_sync(0xffffffffu, s, off);
    float mean = s * (1.f / HS);

    float d0 = x0.x - mean, d1 = x0.y - mean, d2 = x0.z - mean, d3 = x0.w - mean;
    float d4 = x1.x - mean, d5 = x1.y - mean, d6 = x1.z - mean, d7 = x1.w - mean;
    float ss = d0 * d0 + d1 * d1 + d2 * d2 + d3 * d3 + d4 * d4 + d5 * d5 + d6 * d6 + d7 * d7;
    #pragma unroll
    for (int off = 16; off; off >>= 1) ss += __shfl_xor_sync(0xffffffffu, ss, off);
    float rstd = rsqrtf(ss * (1.f / HS) + 1e-5f);

    const float4* gr = (const float4*)gamma;
    const float4* br = (const float4*)beta;
    float4 gg0 = gr[2 * lane], gg1 = gr[2 * lane + 1];
    float4 bb0 = br[2 * lane], bb1 = br[2 * lane + 1];

    float o0 = d0 * rstd * gg0.x + bb0.x;
    float o1 = d1 * rstd * gg0.y + bb0.y;
    float o2 = d2 * rstd * gg0.z + bb0.z;
    float o3 = d3 * rstd * gg0.w + bb0.w;
    float o4 = d4 * rstd * gg1.x + bb1.x;
    float o5 = d5 * rstd * gg1.y + bb1.y;
    float o6 = d6 * rstd * gg1.z + bb1.z;
    float o7 = d7 * rstd * gg1.w + bb1.w;

    float4* orow = (float4*)(out + (size_t)gw * HS);
    orow[2 * lane]     = make_float4(o0, o1, o2, o3);
    orow[2 * lane + 1] = make_float4(o4, o5, o6, o7);

    if (outbf) {
        uint4 w;
        w.x = packbf2(o0, o1); w.y = packbf2(o2, o3);
        w.z = packbf2(o4, o5); w.w = packbf2(o6, o7);
        *(uint4*)(outbf + (size_t)gw * (HS / 2) + 4 * lane) = w;
    }
}

// ---------------- host orchestration ----------------
extern "C" void kernel_launch(void* const* d_in, const int* in_sizes, int n_in,
                              void* d_out, int out_size)
{
    const float* x_in     = (const float*)d_in[0];
    const int*   edge_feat= (const int*)  d_in[1];
    const int*   src      = (const int*)  d_in[2];
    const int*   dst      = (const int*)  d_in[3];
    const float* rel      = (const float*)d_in[4];
    const float* Wq       = (const float*)d_in[5];
    const float* bq       = (const float*)d_in[6];
    const float* Wk       = (const float*)d_in[7];
    const float* Wv       = (const float*)d_in[8];
    const float* Wo       = (const float*)d_in[9];
    const float* bo       = (const float*)d_in[10];
    const float* W1       = (const float*)d_in[11];
    const float* b1       = (const float*)d_in[12];
    const float* W2       = (const float*)d_in[13];
    const float* b2       = (const float*)d_in[14];
    const float* ln1g     = (const float*)d_in[15];
    const float* ln1b     = (const float*)d_in[16];
    const float* ln2g     = (const float*)d_in[17];
    const float* ln2b     = (const float*)d_in[18];

    float *q, *k, *tmp, *h, *xbuf;
    uint32_t *xbf, *vbf, *obf, *hbf, *ffbf, *wbf;
    int* cnt;
    cudaGetSymbolAddress((void**)&q,    g_q);
    cudaGetSymbolAddress((void**)&k,    g_k);
    cudaGetSymbolAddress((void**)&tmp,  g_tmp);
    cudaGetSymbolAddress((void**)&h,    g_h);
    cudaGetSymbolAddress((void**)&xbuf, g_xbuf);
    cudaGetSymbolAddress((void**)&xbf,  g_xbf);
    cudaGetSymbolAddress((void**)&vbf,  g_vbf);
    cudaGetSymbolAddress((void**)&obf,  g_obf);
    cudaGetSymbolAddress((void**)&hbf,  g_hbf);
    cudaGetSymbolAddress((void**)&ffbf, g_ffbf);
    cudaGetSymbolAddress((void**)&wbf,  g_wbf);
    cudaGetSymbolAddress((void**)&cnt,  g_cnt);

    // lazily-created side stream + fork/join events (resource caching only;
    // identical graph work every call)
    static cudaStream_t s2 = nullptr;
    static cudaEvent_t evFork = nullptr, evJoin = nullptr;
    if (s2 == nullptr) {
        cudaStreamCreateWithFlags(&s2, cudaStreamNonBlocking);
        cudaEventCreateWithFlags(&evFork, cudaEventDisableTiming);
        cudaEventCreateWithFlags(&evJoin, cudaEventDisableTiming);
    }

    // opt-in to 64KB dynamic smem (idempotent; not a stream op)
    cudaFuncSetAttribute(bf16_gemm_qkv_kernel,
                         cudaFuncAttributeMaxDynamicSharedMemorySize, GEMM_SMEM_BYTES);
    cudaFuncSetAttribute(bf16_gemm_kernel<2, false>,
                         cudaFuncAttributeMaxDynamicSharedMemorySize, GEMM_SMEM_BYTES);
    cudaFuncSetAttribute(bf16_gemm_kernel<1, true>,
                         cudaFuncAttributeMaxDynamicSharedMemorySize, GEMM_SMEM_BYTES);

    // ---- fork: CSR chain on side stream, overlapped with converts + layer-0 qkv ----
    cudaEventRecord(evFork, 0);
    cudaStreamWaitEvent(s2, evFork, 0);
    cudaMemsetAsync(cnt, 0, N_NODES * sizeof(int), s2);
    hist_kernel<<<(N_EDGES + 255) / 256, 256, 0, s2>>>(dst);
    scan_kernel<<<1, 1024, 0, s2>>>();
    scatter_kernel<<<(N_EDGES + 255) / 256, 256, 0, s2>>>(dst);
    cudaEventRecord(evJoin, s2);

    // main stream: operand conversion
    convert_weights_kernel<<<(2 * WL_STRIDE + 255) / 256, 256>>>(Wq, Wk, Wv, Wo, W1, W2);
    convert_x_kernel<<<(N_NODES * HS / 2 + 255) / 256, 256>>>(x_in);

    const int warp_blocks = (N_NODES * 32 + 255) / 256;
    const int GM = (N_NODES + BM - 1) / BM;   // 157
    const int gnHS = HS / BN;                  // 2
    const int gnFF = FF_DIM / BN;              // 8
    const int tilesHS = GM * gnHS;             // 314
    const int tilesFF = GM * gnFF;             // 1256
    const int PGRID = 296;

    const float* xres = x_in;
    for (int l = 0; l < N_LAYERS; l++) {
        const uint32_t* wl = wbf + (size_t)l * WL_STRIDE;

        bf16_gemm_qkv_kernel<<<PGRID, 256, GEMM_SMEM_BYTES>>>(
            N_NODES, HS, HS, gnHS, tilesHS,
            xbf, wl + WQ_OFF, wl + WK_OFF, wl + WV_OFF,
            bq + l * HS, q, k, vbf);

        if (l == 0) cudaStreamWaitEvent(0, evJoin, 0);   // join CSR before first edge pass
        edge_agg_kernel<<<warp_blocks, 256>>>(rel, edge_feat, src);

        bf16_gemm_kernel<2, false><<<PGRID, 256, GEMM_SMEM_BYTES>>>(
            N_NODES, HS, HS, gnHS, tilesHS,
            obf, wl + WO_OFF, bo + l * HS, xres, tmp, nullptr);
        ln_kernel<<<warp_blocks, 256>>>(tmp, ln1g + l * HS, ln1b + l * HS, h, hbf);

        bf16_gemm_kernel<1, true><<<PGRID, 256, GEMM_SMEM_BYTES>>>(
            N_NODES, HS, FF_DIM, gnFF, tilesFF,
            hbf, wl + W1_OFF, b1 + l * FF_DIM, nullptr, nullptr, ffbf);
        bf16_gemm_kernel<2, false><<<PGRID, 256, GEMM_SMEM_BYTES>>>(
            N_NODES, FF_DIM, HS, gnHS, tilesHS,
            ffbf, wl + W2_OFF, b2 + l * HS, h, tmp, nullptr);

        if (l == N_LAYERS - 1) {
            ln_kernel<<<warp_blocks, 256>>>(tmp, ln2g + l * HS, ln2b + l * HS, (float*)d_out, nullptr);
        } else {
            ln_kernel<<<warp_blocks, 256>>>(tmp, ln2g + l * HS, ln2b + l * HS, xbuf, xbf);
            xres = xbuf;
        }
    }
}